// round 3
// baseline (speedup 1.0000x reference)
#include <cuda_runtime.h>
#include <math.h>

// Problem dims (fixed per reference setup_inputs)
#define BSZ 8
#define SEQ 2048
#define DIM 1024
#define HID 4096
#define ROWS (BSZ * SEQ)   // 16384

// ---------------------------------------------------------------------------
// Static device scratch (no cudaMalloc allowed)
// ---------------------------------------------------------------------------
static __device__ float g_h [(size_t)ROWS * DIM];          // ln1(x)
static __device__ float g_q [(size_t)ROWS * DIM];
static __device__ float g_k [(size_t)ROWS * DIM];
static __device__ float g_v [(size_t)ROWS * DIM];
static __device__ float g_s [(size_t)BSZ * SEQ * SEQ];     // attention scores / probs
static __device__ float g_av[(size_t)ROWS * DIM];          // a @ v
static __device__ float g_x2[(size_t)ROWS * DIM];          // h + attn_out
static __device__ float g_h2[(size_t)ROWS * DIM];          // ln2(x2)
static __device__ float g_f [(size_t)ROWS * HID];          // gelu(h2@w1+b1)

// ---------------------------------------------------------------------------
// LayerNorm: one block per row, 256 threads, D=1024 via float4
// ---------------------------------------------------------------------------
__global__ __launch_bounds__(256) void ln_kernel(
    const float* __restrict__ x, const float* __restrict__ g,
    const float* __restrict__ b, float* __restrict__ out)
{
    __shared__ float red0[256];
    __shared__ float red1[256];
    const int tid = threadIdx.x;
    const size_t row = blockIdx.x;
    const float4 v = reinterpret_cast<const float4*>(x + row * DIM)[tid];

    float s  = v.x + v.y + v.z + v.w;
    float sq = v.x * v.x + v.y * v.y + v.z * v.z + v.w * v.w;
    red0[tid] = s; red1[tid] = sq;
    __syncthreads();
    for (int off = 128; off > 0; off >>= 1) {
        if (tid < off) { red0[tid] += red0[tid + off]; red1[tid] += red1[tid + off]; }
        __syncthreads();
    }
    const float mu  = red0[0] * (1.0f / DIM);
    const float var = red1[0] * (1.0f / DIM) - mu * mu;
    const float inv = rsqrtf(var + 1e-5f);

    const float4 gg = reinterpret_cast<const float4*>(g)[tid];
    const float4 bb = reinterpret_cast<const float4*>(b)[tid];
    float4 o;
    o.x = (v.x - mu) * inv * gg.x + bb.x;
    o.y = (v.y - mu) * inv * gg.y + bb.y;
    o.z = (v.z - mu) * inv * gg.z + bb.z;
    o.w = (v.w - mu) * inv * gg.w + bb.w;
    reinterpret_cast<float4*>(out + row * DIM)[tid] = o;
}

// ---------------------------------------------------------------------------
// Row softmax: one block per row of length SEQ=2048, 256 threads, 8 vals/thr
// ---------------------------------------------------------------------------
__global__ __launch_bounds__(256) void softmax_kernel(float* __restrict__ sm)
{
    __shared__ float red[256];
    const int tid = threadIdx.x;
    float4* p4 = reinterpret_cast<float4*>(sm + (size_t)blockIdx.x * SEQ);
    float4 v0 = p4[tid];
    float4 v1 = p4[tid + 256];

    float m = fmaxf(fmaxf(fmaxf(v0.x, v0.y), fmaxf(v0.z, v0.w)),
                    fmaxf(fmaxf(v1.x, v1.y), fmaxf(v1.z, v1.w)));
    red[tid] = m;
    __syncthreads();
    for (int off = 128; off > 0; off >>= 1) {
        if (tid < off) red[tid] = fmaxf(red[tid], red[tid + off]);
        __syncthreads();
    }
    m = red[0];
    __syncthreads();

    v0.x = __expf(v0.x - m); v0.y = __expf(v0.y - m);
    v0.z = __expf(v0.z - m); v0.w = __expf(v0.w - m);
    v1.x = __expf(v1.x - m); v1.y = __expf(v1.y - m);
    v1.z = __expf(v1.z - m); v1.w = __expf(v1.w - m);

    float s = v0.x + v0.y + v0.z + v0.w + v1.x + v1.y + v1.z + v1.w;
    red[tid] = s;
    __syncthreads();
    for (int off = 128; off > 0; off >>= 1) {
        if (tid < off) red[tid] += red[tid + off];
        __syncthreads();
    }
    const float inv = 1.0f / red[0];

    v0.x *= inv; v0.y *= inv; v0.z *= inv; v0.w *= inv;
    v1.x *= inv; v1.y *= inv; v1.z *= inv; v1.w *= inv;
    p4[tid] = v0;
    p4[tid + 256] = v1;
}

// ---------------------------------------------------------------------------
// Tiled SGEMM: C = epilogue(alpha * A@B (+bias) (+res)), optional GELU.
//   A: [M,K] row-major.  B: [K,N] row-major (TRANSB=false) or [N,K] (TRANSB=true).
//   Batched over blockIdx.z via element strides. All of M,N multiples of 128,
//   K multiple of 8 (guaranteed by the problem dims) -> no bounds checks.
// ---------------------------------------------------------------------------
template <bool TRANSB, bool GELU>
__global__ __launch_bounds__(256) void gemm_kernel(
    const float* __restrict__ A, const float* __restrict__ Bm,
    float* __restrict__ C, int M, int N, int K,
    long long sA, long long sB, long long sC,
    float alpha, const float* __restrict__ bias,
    const float* __restrict__ res, long long sRes)
{
    __shared__ float As[8][128];
    __shared__ float Bs[8][128];

    const int tid = threadIdx.x;
    const int tx = tid & 15;      // col group
    const int ty = tid >> 4;      // row group

    const float* Ap = A + blockIdx.z * sA + (size_t)(blockIdx.y * 128) * K;
    const float* Bp;
    if (TRANSB) Bp = Bm + blockIdx.z * sB + (size_t)(blockIdx.x * 128) * K;
    else        Bp = Bm + blockIdx.z * sB + (size_t)(blockIdx.x * 128);

    const int ar = tid >> 1;
    const int ac = (tid & 1) * 4;
    const int brNN = tid >> 5;
    const int bcNN = (tid & 31) * 4;

    float acc[8][8];
#pragma unroll
    for (int i = 0; i < 8; ++i)
#pragma unroll
        for (int j = 0; j < 8; ++j) acc[i][j] = 0.0f;

    const int kt = K >> 3;
    for (int t = 0; t < kt; ++t) {
        const int k0 = t * 8;
        // Stage A (transposed into smem: As[k][m])
        const float4 av = *reinterpret_cast<const float4*>(Ap + (size_t)ar * K + k0 + ac);
        As[ac + 0][ar] = av.x; As[ac + 1][ar] = av.y;
        As[ac + 2][ar] = av.z; As[ac + 3][ar] = av.w;
        // Stage B (Bs[k][n])
        if (TRANSB) {
            const float4 bv = *reinterpret_cast<const float4*>(Bp + (size_t)ar * K + k0 + ac);
            Bs[ac + 0][ar] = bv.x; Bs[ac + 1][ar] = bv.y;
            Bs[ac + 2][ar] = bv.z; Bs[ac + 3][ar] = bv.w;
        } else {
            const float4 bv = *reinterpret_cast<const float4*>(Bp + (size_t)(k0 + brNN) * N + bcNN);
            *reinterpret_cast<float4*>(&Bs[brNN][bcNN]) = bv;
        }
        __syncthreads();

#pragma unroll
        for (int k = 0; k < 8; ++k) {
            const float4 a0 = *reinterpret_cast<const float4*>(&As[k][ty * 8]);
            const float4 a1 = *reinterpret_cast<const float4*>(&As[k][ty * 8 + 4]);
            const float4 b0 = *reinterpret_cast<const float4*>(&Bs[k][tx * 8]);
            const float4 b1 = *reinterpret_cast<const float4*>(&Bs[k][tx * 8 + 4]);
            const float a[8] = {a0.x, a0.y, a0.z, a0.w, a1.x, a1.y, a1.z, a1.w};
            const float b[8] = {b0.x, b0.y, b0.z, b0.w, b1.x, b1.y, b1.z, b1.w};
#pragma unroll
            for (int i = 0; i < 8; ++i)
#pragma unroll
                for (int j = 0; j < 8; ++j) acc[i][j] = fmaf(a[i], b[j], acc[i][j]);
        }
        __syncthreads();
    }

    // Epilogue
    const int rowBase = blockIdx.y * 128 + ty * 8;
    const int colBase = blockIdx.x * 128 + tx * 8;
    float* Cb = C + blockIdx.z * sC;
    const float* Rb = res ? res + blockIdx.z * sRes : nullptr;

    float bsum[8];
    if (bias) {
        const float4 bi0 = *reinterpret_cast<const float4*>(bias + colBase);
        const float4 bi1 = *reinterpret_cast<const float4*>(bias + colBase + 4);
        bsum[0] = bi0.x; bsum[1] = bi0.y; bsum[2] = bi0.z; bsum[3] = bi0.w;
        bsum[4] = bi1.x; bsum[5] = bi1.y; bsum[6] = bi1.z; bsum[7] = bi1.w;
    } else {
#pragma unroll
        for (int j = 0; j < 8; ++j) bsum[j] = 0.0f;
    }

#pragma unroll
    for (int i = 0; i < 8; ++i) {
        const size_t roff = (size_t)(rowBase + i) * N + colBase;
        float out[8];
#pragma unroll
        for (int j = 0; j < 8; ++j) out[j] = acc[i][j] * alpha + bsum[j];
        if (Rb) {
            const float4 r0 = *reinterpret_cast<const float4*>(Rb + roff);
            const float4 r1 = *reinterpret_cast<const float4*>(Rb + roff + 4);
            out[0] += r0.x; out[1] += r0.y; out[2] += r0.z; out[3] += r0.w;
            out[4] += r1.x; out[5] += r1.y; out[6] += r1.z; out[7] += r1.w;
        }
        if (GELU) {
#pragma unroll
            for (int j = 0; j < 8; ++j)
                out[j] = 0.5f * out[j] * (1.0f + erff(out[j] * 0.70710678118654752f));
        }
        float4 o0 = {out[0], out[1], out[2], out[3]};
        float4 o1 = {out[4], out[5], out[6], out[7]};
        *reinterpret_cast<float4*>(Cb + roff)     = o0;
        *reinterpret_cast<float4*>(Cb + roff + 4) = o1;
    }
}

// ---------------------------------------------------------------------------
// Launch
// ---------------------------------------------------------------------------
extern "C" void kernel_launch(void* const* d_in, const int* in_sizes, int n_in,
                              void* d_out, int out_size)
{
    const float* x     = (const float*)d_in[0];
    const float* ln1_g = (const float*)d_in[1];
    const float* ln1_b = (const float*)d_in[2];
    const float* wq    = (const float*)d_in[3];
    const float* wk    = (const float*)d_in[4];
    const float* wv    = (const float*)d_in[5];
    const float* wo    = (const float*)d_in[6];
    const float* ln2_g = (const float*)d_in[7];
    const float* ln2_b = (const float*)d_in[8];
    const float* w1    = (const float*)d_in[9];
    const float* b1    = (const float*)d_in[10];
    const float* w2    = (const float*)d_in[11];
    const float* b2    = (const float*)d_in[12];
    float* out = (float*)d_out;

    void* p;
    cudaGetSymbolAddress(&p, g_h);  float* ph  = (float*)p;
    cudaGetSymbolAddress(&p, g_q);  float* pq  = (float*)p;
    cudaGetSymbolAddress(&p, g_k);  float* pk  = (float*)p;
    cudaGetSymbolAddress(&p, g_v);  float* pv  = (float*)p;
    cudaGetSymbolAddress(&p, g_s);  float* ps  = (float*)p;
    cudaGetSymbolAddress(&p, g_av); float* pav = (float*)p;
    cudaGetSymbolAddress(&p, g_x2); float* px2 = (float*)p;
    cudaGetSymbolAddress(&p, g_h2); float* ph2 = (float*)p;
    cudaGetSymbolAddress(&p, g_f);  float* pf  = (float*)p;

    const dim3 blk(256);
    const float SCALE = 0.03125f;  // 1/sqrt(1024)

    // 1. h = ln1(x)
    ln_kernel<<<ROWS, blk>>>(x, ln1_g, ln1_b, ph);

    // 2. q, k, v = h @ {wq, wk, wv}   [16384,1024]x[1024,1024]
    {
        dim3 grid(DIM / 128, ROWS / 128, 1);
        gemm_kernel<false, false><<<grid, blk>>>(ph, wq, pq, ROWS, DIM, DIM, 0, 0, 0, 1.0f, nullptr, nullptr, 0);
        gemm_kernel<false, false><<<grid, blk>>>(ph, wk, pk, ROWS, DIM, DIM, 0, 0, 0, 1.0f, nullptr, nullptr, 0);
        gemm_kernel<false, false><<<grid, blk>>>(ph, wv, pv, ROWS, DIM, DIM, 0, 0, 0, 1.0f, nullptr, nullptr, 0);
    }

    // 3. s = (q @ k^T) * scale   per batch: [2048,1024] x [2048,1024]^T
    {
        dim3 grid(SEQ / 128, SEQ / 128, BSZ);
        gemm_kernel<true, false><<<grid, blk>>>(pq, pk, ps, SEQ, SEQ, DIM,
            (long long)SEQ * DIM, (long long)SEQ * DIM, (long long)SEQ * SEQ,
            SCALE, nullptr, nullptr, 0);
    }

    // 4. softmax rows
    softmax_kernel<<<BSZ * SEQ, blk>>>(ps);

    // 5. av = a @ v   per batch: [2048,2048] x [2048,1024]
    {
        dim3 grid(DIM / 128, SEQ / 128, BSZ);
        gemm_kernel<false, false><<<grid, blk>>>(ps, pv, pav, SEQ, DIM, SEQ,
            (long long)SEQ * SEQ, (long long)SEQ * DIM, (long long)SEQ * DIM,
            1.0f, nullptr, nullptr, 0);
    }

    // 6. x2 = h + av @ wo   [16384,1024]x[1024,1024], residual = h
    {
        dim3 grid(DIM / 128, ROWS / 128, 1);
        gemm_kernel<false, false><<<grid, blk>>>(pav, wo, px2, ROWS, DIM, DIM, 0, 0, 0,
            1.0f, nullptr, ph, 0);
    }

    // 7. h2 = ln2(x2)
    ln_kernel<<<ROWS, blk>>>(px2, ln2_g, ln2_b, ph2);

    // 8. f = gelu(h2 @ w1 + b1)   [16384,1024]x[1024,4096]
    {
        dim3 grid(HID / 128, ROWS / 128, 1);
        gemm_kernel<false, true><<<grid, blk>>>(ph2, w1, pf, ROWS, HID, DIM, 0, 0, 0,
            1.0f, b1, nullptr, 0);
    }

    // 9. out = x2 + f @ w2 + b2   [16384,4096]x[4096,1024]
    {
        dim3 grid(DIM / 128, ROWS / 128, 1);
        gemm_kernel<false, false><<<grid, blk>>>(pf, w2, out, ROWS, DIM, HID, 0, 0, 0,
            1.0f, b2, px2, 0);
    }
}

// round 4
// speedup vs baseline: 1.0016x; 1.0016x over previous
#include <cuda_runtime.h>
#include <math.h>

// Problem dims (fixed per reference setup_inputs)
#define BSZ 8
#define SEQ 2048
#define DIM 1024
#define HID 4096
#define ROWS (BSZ * SEQ)   // 16384

// ---------------------------------------------------------------------------
// Static device scratch (no cudaMalloc allowed)
// ---------------------------------------------------------------------------
static __device__ float g_h [(size_t)ROWS * DIM];          // ln1(x)
static __device__ float g_q [(size_t)ROWS * DIM];
static __device__ float g_k [(size_t)ROWS * DIM];
static __device__ float g_v [(size_t)ROWS * DIM];
static __device__ float g_s [(size_t)BSZ * SEQ * SEQ];     // attention scores / probs
static __device__ float g_av[(size_t)ROWS * DIM];          // a @ v
static __device__ float g_x2[(size_t)ROWS * DIM];          // h + attn_out
static __device__ float g_h2[(size_t)ROWS * DIM];          // ln2(x2)
static __device__ float g_f [(size_t)ROWS * HID];          // gelu(h2@w1+b1)

// ---------------------------------------------------------------------------
// LayerNorm: one block per row, 256 threads, D=1024 via float4
// ---------------------------------------------------------------------------
__global__ __launch_bounds__(256) void ln_kernel(
    const float* __restrict__ x, const float* __restrict__ g,
    const float* __restrict__ b, float* __restrict__ out)
{
    __shared__ float red0[256];
    __shared__ float red1[256];
    const int tid = threadIdx.x;
    const size_t row = blockIdx.x;
    const float4 v = reinterpret_cast<const float4*>(x + row * DIM)[tid];

    float s  = v.x + v.y + v.z + v.w;
    float sq = v.x * v.x + v.y * v.y + v.z * v.z + v.w * v.w;
    red0[tid] = s; red1[tid] = sq;
    __syncthreads();
    for (int off = 128; off > 0; off >>= 1) {
        if (tid < off) { red0[tid] += red0[tid + off]; red1[tid] += red1[tid + off]; }
        __syncthreads();
    }
    const float mu  = red0[0] * (1.0f / DIM);
    const float var = red1[0] * (1.0f / DIM) - mu * mu;
    const float inv = rsqrtf(var + 1e-5f);

    const float4 gg = reinterpret_cast<const float4*>(g)[tid];
    const float4 bb = reinterpret_cast<const float4*>(b)[tid];
    float4 o;
    o.x = (v.x - mu) * inv * gg.x + bb.x;
    o.y = (v.y - mu) * inv * gg.y + bb.y;
    o.z = (v.z - mu) * inv * gg.z + bb.z;
    o.w = (v.w - mu) * inv * gg.w + bb.w;
    reinterpret_cast<float4*>(out + row * DIM)[tid] = o;
}

// ---------------------------------------------------------------------------
// Row softmax: one block per row of length SEQ=2048, 256 threads, 8 vals/thr
// ---------------------------------------------------------------------------
__global__ __launch_bounds__(256) void softmax_kernel(float* __restrict__ sm)
{
    __shared__ float red[256];
    const int tid = threadIdx.x;
    float4* p4 = reinterpret_cast<float4*>(sm + (size_t)blockIdx.x * SEQ);
    float4 v0 = p4[tid];
    float4 v1 = p4[tid + 256];

    float m = fmaxf(fmaxf(fmaxf(v0.x, v0.y), fmaxf(v0.z, v0.w)),
                    fmaxf(fmaxf(v1.x, v1.y), fmaxf(v1.z, v1.w)));
    red[tid] = m;
    __syncthreads();
    for (int off = 128; off > 0; off >>= 1) {
        if (tid < off) red[tid] = fmaxf(red[tid], red[tid + off]);
        __syncthreads();
    }
    m = red[0];
    __syncthreads();

    v0.x = __expf(v0.x - m); v0.y = __expf(v0.y - m);
    v0.z = __expf(v0.z - m); v0.w = __expf(v0.w - m);
    v1.x = __expf(v1.x - m); v1.y = __expf(v1.y - m);
    v1.z = __expf(v1.z - m); v1.w = __expf(v1.w - m);

    float s = v0.x + v0.y + v0.z + v0.w + v1.x + v1.y + v1.z + v1.w;
    red[tid] = s;
    __syncthreads();
    for (int off = 128; off > 0; off >>= 1) {
        if (tid < off) red[tid] += red[tid + off];
        __syncthreads();
    }
    const float inv = 1.0f / red[0];

    v0.x *= inv; v0.y *= inv; v0.z *= inv; v0.w *= inv;
    v1.x *= inv; v1.y *= inv; v1.z *= inv; v1.w *= inv;
    p4[tid] = v0;
    p4[tid + 256] = v1;
}

// ---------------------------------------------------------------------------
// Tiled SGEMM: C = epilogue(alpha * A@B (+bias) (+res)), optional GELU.
//   A: [M,K] row-major.  B: [K,N] row-major (TRANSB=false) or [N,K] (TRANSB=true).
//   Batched over blockIdx.z via element strides. All of M,N multiples of 128,
//   K multiple of 8 (guaranteed by the problem dims) -> no bounds checks.
// ---------------------------------------------------------------------------
template <bool TRANSB, bool GELU>
__global__ __launch_bounds__(256) void gemm_kernel(
    const float* __restrict__ A, const float* __restrict__ Bm,
    float* __restrict__ C, int M, int N, int K,
    long long sA, long long sB, long long sC,
    float alpha, const float* __restrict__ bias,
    const float* __restrict__ res, long long sRes)
{
    __shared__ float As[8][128];
    __shared__ float Bs[8][128];

    const int tid = threadIdx.x;
    const int tx = tid & 15;      // col group
    const int ty = tid >> 4;      // row group

    const float* Ap = A + blockIdx.z * sA + (size_t)(blockIdx.y * 128) * K;
    const float* Bp;
    if (TRANSB) Bp = Bm + blockIdx.z * sB + (size_t)(blockIdx.x * 128) * K;
    else        Bp = Bm + blockIdx.z * sB + (size_t)(blockIdx.x * 128);

    const int ar = tid >> 1;
    const int ac = (tid & 1) * 4;
    const int brNN = tid >> 5;
    const int bcNN = (tid & 31) * 4;

    float acc[8][8];
#pragma unroll
    for (int i = 0; i < 8; ++i)
#pragma unroll
        for (int j = 0; j < 8; ++j) acc[i][j] = 0.0f;

    const int kt = K >> 3;
    for (int t = 0; t < kt; ++t) {
        const int k0 = t * 8;
        // Stage A (transposed into smem: As[k][m])
        const float4 av = *reinterpret_cast<const float4*>(Ap + (size_t)ar * K + k0 + ac);
        As[ac + 0][ar] = av.x; As[ac + 1][ar] = av.y;
        As[ac + 2][ar] = av.z; As[ac + 3][ar] = av.w;
        // Stage B (Bs[k][n])
        if (TRANSB) {
            const float4 bv = *reinterpret_cast<const float4*>(Bp + (size_t)ar * K + k0 + ac);
            Bs[ac + 0][ar] = bv.x; Bs[ac + 1][ar] = bv.y;
            Bs[ac + 2][ar] = bv.z; Bs[ac + 3][ar] = bv.w;
        } else {
            const float4 bv = *reinterpret_cast<const float4*>(Bp + (size_t)(k0 + brNN) * N + bcNN);
            *reinterpret_cast<float4*>(&Bs[brNN][bcNN]) = bv;
        }
        __syncthreads();

#pragma unroll
        for (int k = 0; k < 8; ++k) {
            const float4 a0 = *reinterpret_cast<const float4*>(&As[k][ty * 8]);
            const float4 a1 = *reinterpret_cast<const float4*>(&As[k][ty * 8 + 4]);
            const float4 b0 = *reinterpret_cast<const float4*>(&Bs[k][tx * 8]);
            const float4 b1 = *reinterpret_cast<const float4*>(&Bs[k][tx * 8 + 4]);
            const float a[8] = {a0.x, a0.y, a0.z, a0.w, a1.x, a1.y, a1.z, a1.w};
            const float b[8] = {b0.x, b0.y, b0.z, b0.w, b1.x, b1.y, b1.z, b1.w};
#pragma unroll
            for (int i = 0; i < 8; ++i)
#pragma unroll
                for (int j = 0; j < 8; ++j) acc[i][j] = fmaf(a[i], b[j], acc[i][j]);
        }
        __syncthreads();
    }

    // Epilogue
    const int rowBase = blockIdx.y * 128 + ty * 8;
    const int colBase = blockIdx.x * 128 + tx * 8;
    float* Cb = C + blockIdx.z * sC;
    const float* Rb = res ? res + blockIdx.z * sRes : nullptr;

    float bsum[8];
    if (bias) {
        const float4 bi0 = *reinterpret_cast<const float4*>(bias + colBase);
        const float4 bi1 = *reinterpret_cast<const float4*>(bias + colBase + 4);
        bsum[0] = bi0.x; bsum[1] = bi0.y; bsum[2] = bi0.z; bsum[3] = bi0.w;
        bsum[4] = bi1.x; bsum[5] = bi1.y; bsum[6] = bi1.z; bsum[7] = bi1.w;
    } else {
#pragma unroll
        for (int j = 0; j < 8; ++j) bsum[j] = 0.0f;
    }

#pragma unroll
    for (int i = 0; i < 8; ++i) {
        const size_t roff = (size_t)(rowBase + i) * N + colBase;
        float out[8];
#pragma unroll
        for (int j = 0; j < 8; ++j) out[j] = acc[i][j] * alpha + bsum[j];
        if (Rb) {
            const float4 r0 = *reinterpret_cast<const float4*>(Rb + roff);
            const float4 r1 = *reinterpret_cast<const float4*>(Rb + roff + 4);
            out[0] += r0.x; out[1] += r0.y; out[2] += r0.z; out[3] += r0.w;
            out[4] += r1.x; out[5] += r1.y; out[6] += r1.z; out[7] += r1.w;
        }
        if (GELU) {
#pragma unroll
            for (int j = 0; j < 8; ++j)
                out[j] = 0.5f * out[j] * (1.0f + erff(out[j] * 0.70710678118654752f));
        }
        float4 o0 = {out[0], out[1], out[2], out[3]};
        float4 o1 = {out[4], out[5], out[6], out[7]};
        *reinterpret_cast<float4*>(Cb + roff)     = o0;
        *reinterpret_cast<float4*>(Cb + roff + 4) = o1;
    }
}

// ---------------------------------------------------------------------------
// Launch
// ---------------------------------------------------------------------------
extern "C" void kernel_launch(void* const* d_in, const int* in_sizes, int n_in,
                              void* d_out, int out_size)
{
    const float* x     = (const float*)d_in[0];
    const float* ln1_g = (const float*)d_in[1];
    const float* ln1_b = (const float*)d_in[2];
    const float* wq    = (const float*)d_in[3];
    const float* wk    = (const float*)d_in[4];
    const float* wv    = (const float*)d_in[5];
    const float* wo    = (const float*)d_in[6];
    const float* ln2_g = (const float*)d_in[7];
    const float* ln2_b = (const float*)d_in[8];
    const float* w1    = (const float*)d_in[9];
    const float* b1    = (const float*)d_in[10];
    const float* w2    = (const float*)d_in[11];
    const float* b2    = (const float*)d_in[12];
    float* out = (float*)d_out;

    void* p;
    cudaGetSymbolAddress(&p, g_h);  float* ph  = (float*)p;
    cudaGetSymbolAddress(&p, g_q);  float* pq  = (float*)p;
    cudaGetSymbolAddress(&p, g_k);  float* pk  = (float*)p;
    cudaGetSymbolAddress(&p, g_v);  float* pv  = (float*)p;
    cudaGetSymbolAddress(&p, g_s);  float* ps  = (float*)p;
    cudaGetSymbolAddress(&p, g_av); float* pav = (float*)p;
    cudaGetSymbolAddress(&p, g_x2); float* px2 = (float*)p;
    cudaGetSymbolAddress(&p, g_h2); float* ph2 = (float*)p;
    cudaGetSymbolAddress(&p, g_f);  float* pf  = (float*)p;

    const dim3 blk(256);
    const float SCALE = 0.03125f;  // 1/sqrt(1024)

    // 1. h = ln1(x)
    ln_kernel<<<ROWS, blk>>>(x, ln1_g, ln1_b, ph);

    // 2. q, k, v = h @ {wq, wk, wv}   [16384,1024]x[1024,1024]
    {
        dim3 grid(DIM / 128, ROWS / 128, 1);
        gemm_kernel<false, false><<<grid, blk>>>(ph, wq, pq, ROWS, DIM, DIM, 0, 0, 0, 1.0f, nullptr, nullptr, 0);
        gemm_kernel<false, false><<<grid, blk>>>(ph, wk, pk, ROWS, DIM, DIM, 0, 0, 0, 1.0f, nullptr, nullptr, 0);
        gemm_kernel<false, false><<<grid, blk>>>(ph, wv, pv, ROWS, DIM, DIM, 0, 0, 0, 1.0f, nullptr, nullptr, 0);
    }

    // 3. s = (q @ k^T) * scale   per batch: [2048,1024] x [2048,1024]^T
    {
        dim3 grid(SEQ / 128, SEQ / 128, BSZ);
        gemm_kernel<true, false><<<grid, blk>>>(pq, pk, ps, SEQ, SEQ, DIM,
            (long long)SEQ * DIM, (long long)SEQ * DIM, (long long)SEQ * SEQ,
            SCALE, nullptr, nullptr, 0);
    }

    // 4. softmax rows
    softmax_kernel<<<BSZ * SEQ, blk>>>(ps);

    // 5. av = a @ v   per batch: [2048,2048] x [2048,1024]
    {
        dim3 grid(DIM / 128, SEQ / 128, BSZ);
        gemm_kernel<false, false><<<grid, blk>>>(ps, pv, pav, SEQ, DIM, SEQ,
            (long long)SEQ * SEQ, (long long)SEQ * DIM, (long long)SEQ * DIM,
            1.0f, nullptr, nullptr, 0);
    }

    // 6. x2 = h + av @ wo   [16384,1024]x[1024,1024], residual = h
    {
        dim3 grid(DIM / 128, ROWS / 128, 1);
        gemm_kernel<false, false><<<grid, blk>>>(pav, wo, px2, ROWS, DIM, DIM, 0, 0, 0,
            1.0f, nullptr, ph, 0);
    }

    // 7. h2 = ln2(x2)
    ln_kernel<<<ROWS, blk>>>(px2, ln2_g, ln2_b, ph2);

    // 8. f = gelu(h2 @ w1 + b1)   [16384,1024]x[1024,4096]
    {
        dim3 grid(HID / 128, ROWS / 128, 1);
        gemm_kernel<false, true><<<grid, blk>>>(ph2, w1, pf, ROWS, HID, DIM, 0, 0, 0,
            1.0f, b1, nullptr, 0);
    }

    // 9. out = x2 + f @ w2 + b2   [16384,4096]x[4096,1024]
    {
        dim3 grid(DIM / 128, ROWS / 128, 1);
        gemm_kernel<false, false><<<grid, blk>>>(pf, w2, out, ROWS, DIM, HID, 0, 0, 0,
            1.0f, b2, px2, 0);
    }
}

// round 7
// speedup vs baseline: 2.8779x; 2.8734x over previous
#include <cuda_runtime.h>
#include <math.h>
#include <stdint.h>

#define BSZ 8
#define SEQ 2048
#define DIM 1024
#define HID 4096
#define ROWS (BSZ*SEQ)

// ---------------- static device scratch ----------------
static __device__ float g_h [(size_t)ROWS*DIM];
static __device__ float g_q [(size_t)ROWS*DIM];
static __device__ float g_k [(size_t)ROWS*DIM];
static __device__ float g_v [(size_t)ROWS*DIM];
static __device__ float g_s [(size_t)BSZ*SEQ*SEQ];
static __device__ float g_av[(size_t)ROWS*DIM];
static __device__ float g_x2[(size_t)ROWS*DIM];
static __device__ float g_h2[(size_t)ROWS*DIM];
static __device__ float g_f [(size_t)ROWS*HID];
static __device__ float g_wq[(size_t)DIM*DIM];
static __device__ float g_wk[(size_t)DIM*DIM];
static __device__ float g_wv[(size_t)DIM*DIM];
static __device__ float g_wo[(size_t)DIM*DIM];
static __device__ float g_w1[(size_t)DIM*HID];
static __device__ float g_w2[(size_t)HID*DIM];

// ---------------- helpers ----------------
__device__ __forceinline__ uint32_t smem_u32(const void* p) {
    uint32_t a;
    asm("{ .reg .u64 t; cvta.to.shared.u64 t, %1; cvt.u32.u64 %0, t; }" : "=r"(a) : "l"(p));
    return a;
}
__device__ __forceinline__ float rtf32(float v) {
    uint32_t u;
    asm("cvt.rna.tf32.f32 %0, %1;" : "=r"(u) : "f"(v));
    return __uint_as_float(u);
}
__device__ __forceinline__ void cp16(uint32_t dst, const void* src) {
    asm volatile("cp.async.cg.shared.global [%0], [%1], 16;" :: "r"(dst), "l"(src));
}
#define CP_COMMIT() asm volatile("cp.async.commit_group;")
#define CP_WAIT2()  asm volatile("cp.async.wait_group 2;")

#define MMA_TF32(d, a, b) \
    asm volatile("mma.sync.aligned.m16n8k8.row.col.f32.tf32.tf32.f32 " \
        "{%0,%1,%2,%3}, {%4,%5,%6,%7}, {%8,%9}, {%0,%1,%2,%3};" \
        : "+f"((d)[0]), "+f"((d)[1]), "+f"((d)[2]), "+f"((d)[3]) \
        : "r"((a)[0]), "r"((a)[1]), "r"((a)[2]), "r"((a)[3]), \
          "r"((b)[0]), "r"((b)[1]))

// ---------------- tf32 round kernel (weights) ----------------
__global__ __launch_bounds__(256) void round_kernel(
    const float* __restrict__ in, float* __restrict__ out, int n4)
{
    const int idx = blockIdx.x * 256 + threadIdx.x;
    if (idx < n4) {
        float4 v = reinterpret_cast<const float4*>(in)[idx];
        v.x = rtf32(v.x); v.y = rtf32(v.y); v.z = rtf32(v.z); v.w = rtf32(v.w);
        reinterpret_cast<float4*>(out)[idx] = v;
    }
}

// ---------------- LayerNorm (tf32-rounded output) ----------------
__global__ __launch_bounds__(256) void ln_kernel(
    const float* __restrict__ x, const float* __restrict__ g,
    const float* __restrict__ b, float* __restrict__ out)
{
    __shared__ float r0[256], r1[256];
    const int tid = threadIdx.x;
    const size_t row = blockIdx.x;
    const float4 v = reinterpret_cast<const float4*>(x + row * DIM)[tid];
    r0[tid] = v.x + v.y + v.z + v.w;
    r1[tid] = v.x*v.x + v.y*v.y + v.z*v.z + v.w*v.w;
    __syncthreads();
    for (int off = 128; off > 0; off >>= 1) {
        if (tid < off) { r0[tid] += r0[tid+off]; r1[tid] += r1[tid+off]; }
        __syncthreads();
    }
    const float mu  = r0[0] * (1.0f/DIM);
    const float inv = rsqrtf(r1[0] * (1.0f/DIM) - mu*mu + 1e-5f);
    const float4 gg = reinterpret_cast<const float4*>(g)[tid];
    const float4 bb = reinterpret_cast<const float4*>(b)[tid];
    float4 o;
    o.x = rtf32((v.x-mu)*inv*gg.x + bb.x);
    o.y = rtf32((v.y-mu)*inv*gg.y + bb.y);
    o.z = rtf32((v.z-mu)*inv*gg.z + bb.z);
    o.w = rtf32((v.w-mu)*inv*gg.w + bb.w);
    reinterpret_cast<float4*>(out + row * DIM)[tid] = o;
}

// ---------------- softmax (tf32-rounded probs) ----------------
__global__ __launch_bounds__(256) void softmax_kernel(float* __restrict__ sm)
{
    __shared__ float red[256];
    const int tid = threadIdx.x;
    float4* p4 = reinterpret_cast<float4*>(sm + (size_t)blockIdx.x * SEQ);
    float4 v0 = p4[tid], v1 = p4[tid + 256];
    float m = fmaxf(fmaxf(fmaxf(v0.x,v0.y), fmaxf(v0.z,v0.w)),
                    fmaxf(fmaxf(v1.x,v1.y), fmaxf(v1.z,v1.w)));
    red[tid] = m; __syncthreads();
    for (int off = 128; off > 0; off >>= 1) {
        if (tid < off) red[tid] = fmaxf(red[tid], red[tid+off]);
        __syncthreads();
    }
    m = red[0]; __syncthreads();
    v0.x = __expf(v0.x-m); v0.y = __expf(v0.y-m);
    v0.z = __expf(v0.z-m); v0.w = __expf(v0.w-m);
    v1.x = __expf(v1.x-m); v1.y = __expf(v1.y-m);
    v1.z = __expf(v1.z-m); v1.w = __expf(v1.w-m);
    red[tid] = v0.x+v0.y+v0.z+v0.w+v1.x+v1.y+v1.z+v1.w;
    __syncthreads();
    for (int off = 128; off > 0; off >>= 1) {
        if (tid < off) red[tid] += red[tid+off];
        __syncthreads();
    }
    const float inv = 1.0f / red[0];
    v0.x = rtf32(v0.x*inv); v0.y = rtf32(v0.y*inv);
    v0.z = rtf32(v0.z*inv); v0.w = rtf32(v0.w*inv);
    v1.x = rtf32(v1.x*inv); v1.y = rtf32(v1.y*inv);
    v1.z = rtf32(v1.z*inv); v1.w = rtf32(v1.w*inv);
    p4[tid] = v0;
    p4[tid + 256] = v1;
}

// ---------------- TF32 tensor-core GEMM ----------------
// C[M,N] = epi(alpha * A[M,K] @ B) ; B is [K,N] (TRANSB=0) or [N,K] (TRANSB=1).
// Tiles 128x128x16, 8 warps (2x4, warp tile 64x32), 3-stage cp.async pipeline.
// smem per stage: A 128x20 floats (pad), B 128x20 (trans) / 16x136 (normal).
#define STAGE_FLOATS 5120               /* 20480 B */
#define SMEM_GEMM (3 * 20480)

template <bool TRANSB>
__device__ __forceinline__ void stage_load(
    uint32_t sbase, int slot, const float* Abase, const float* Bbase,
    int K, int N, int k0, int tid)
{
    const uint32_t sA = sbase + slot * 20480;
    const uint32_t sB = sA + 10240;
#pragma unroll
    for (int h = 0; h < 2; ++h) {
        const int v = tid + h * 256;
        const int row = v >> 2, kv = v & 3;
        cp16(sA + (uint32_t)(row * 80 + kv * 16),
             Abase + (size_t)row * K + k0 + kv * 4);
    }
#pragma unroll
    for (int h = 0; h < 2; ++h) {
        const int v = tid + h * 256;
        if (TRANSB) {
            const int row = v >> 2, kv = v & 3;
            cp16(sB + (uint32_t)(row * 80 + kv * 16),
                 Bbase + (size_t)row * K + k0 + kv * 4);
        } else {
            const int kr = v >> 5, nv = v & 31;
            cp16(sB + (uint32_t)(kr * 544 + nv * 16),
                 Bbase + (size_t)(k0 + kr) * N + nv * 4);
        }
    }
}

template <bool TRANSB, bool GELU, bool ROUND>
__global__ __launch_bounds__(256, 1) void tf32_gemm(
    const float* __restrict__ A, const float* __restrict__ B,
    float* __restrict__ C, int M, int N, int K,
    long long sAa, long long sBb, long long sCc,
    float alpha, const float* __restrict__ bias,
    const float* __restrict__ res)
{
    extern __shared__ float smf[];
    const uint32_t sbase = smem_u32(smf);
    const int tid = threadIdx.x;
    const int lane = tid & 31, wid = tid >> 5;
    const int warpM = wid >> 2, warpN = wid & 3;
    const int lr = lane >> 2, lc = lane & 3;

    const size_t rowBase = (size_t)blockIdx.y * 128;
    const size_t colBase = (size_t)blockIdx.x * 128;
    const float* Abase = A + (size_t)blockIdx.z * sAa + rowBase * K;
    const float* Bbase = TRANSB ? (B + (size_t)blockIdx.z * sBb + colBase * K)
                                : (B + (size_t)blockIdx.z * sBb + colBase);

    float acc[4][4][4];
#pragma unroll
    for (int i = 0; i < 4; ++i)
#pragma unroll
        for (int j = 0; j < 4; ++j)
#pragma unroll
            for (int r = 0; r < 4; ++r) acc[i][j][r] = 0.0f;

    const int KT = K >> 4;
    stage_load<TRANSB>(sbase, 0, Abase, Bbase, K, N, 0, tid);  CP_COMMIT();
    stage_load<TRANSB>(sbase, 1, Abase, Bbase, K, N, 16, tid); CP_COMMIT();

    for (int t = 0; t < KT; ++t) {
        if (t) __syncthreads();
        if (t + 2 < KT)
            stage_load<TRANSB>(sbase, (t + 2) % 3, Abase, Bbase, K, N, (t + 2) * 16, tid);
        CP_COMMIT();
        CP_WAIT2();
        __syncthreads();

        const float* As = smf + (size_t)(t % 3) * STAGE_FLOATS;
        const float* Bs = As + 2560;
#pragma unroll
        for (int kk = 0; kk < 2; ++kk) {
            uint32_t af[4][4], bf[4][2];
#pragma unroll
            for (int i = 0; i < 4; ++i) {
                const float* ap = As + (warpM*64 + i*16 + lr) * 20 + kk*8 + lc;
                af[i][0] = __float_as_uint(ap[0]);
                af[i][1] = __float_as_uint(ap[160]);
                af[i][2] = __float_as_uint(ap[4]);
                af[i][3] = __float_as_uint(ap[164]);
            }
#pragma unroll
            for (int j = 0; j < 4; ++j) {
                if (TRANSB) {
                    const float* bp = Bs + (warpN*32 + j*8 + lr) * 20 + kk*8 + lc;
                    bf[j][0] = __float_as_uint(bp[0]);
                    bf[j][1] = __float_as_uint(bp[4]);
                } else {
                    const float* bp = Bs + (kk*8 + lc) * 136 + warpN*32 + j*8 + lr;
                    bf[j][0] = __float_as_uint(bp[0]);
                    bf[j][1] = __float_as_uint(bp[544]);
                }
            }
#pragma unroll
            for (int i = 0; i < 4; ++i)
#pragma unroll
                for (int j = 0; j < 4; ++j)
                    MMA_TF32(acc[i][j], af[i], bf[j]);
        }
    }

    // ---- epilogue ----
    const size_t zC = (size_t)blockIdx.z * sCc;
#pragma unroll
    for (int i = 0; i < 4; ++i) {
        const size_t r0 = rowBase + warpM*64 + i*16 + lr;
#pragma unroll
        for (int half = 0; half < 2; ++half) {
            const size_t r = r0 + half*8;
#pragma unroll
            for (int j = 0; j < 4; ++j) {
                const size_t c = colBase + warpN*32 + j*8 + 2*lc;
                float v0 = acc[i][j][half*2 + 0] * alpha;
                float v1 = acc[i][j][half*2 + 1] * alpha;
                if (bias) { v0 += bias[c]; v1 += bias[c+1]; }
                if (res) {
                    const float2 rv = *reinterpret_cast<const float2*>(res + r*N + c);
                    v0 += rv.x; v1 += rv.y;
                }
                if (GELU) {
                    v0 = 0.5f * v0 * (1.0f + erff(v0 * 0.70710678118654752f));
                    v1 = 0.5f * v1 * (1.0f + erff(v1 * 0.70710678118654752f));
                }
                if (ROUND) { v0 = rtf32(v0); v1 = rtf32(v1); }
                float2 ov = {v0, v1};
                *reinterpret_cast<float2*>(C + zC + r*N + c) = ov;
            }
        }
    }
}

// ---------------- launch ----------------
extern "C" void kernel_launch(void* const* d_in, const int* in_sizes, int n_in,
                              void* d_out, int out_size)
{
    const float* x     = (const float*)d_in[0];
    const float* ln1_g = (const float*)d_in[1];
    const float* ln1_b = (const float*)d_in[2];
    const float* wq    = (const float*)d_in[3];
    const float* wk    = (const float*)d_in[4];
    const float* wv    = (const float*)d_in[5];
    const float* wo    = (const float*)d_in[6];
    const float* ln2_g = (const float*)d_in[7];
    const float* ln2_b = (const float*)d_in[8];
    const float* w1    = (const float*)d_in[9];
    const float* b1    = (const float*)d_in[10];
    const float* w2    = (const float*)d_in[11];
    const float* b2    = (const float*)d_in[12];
    float* out = (float*)d_out;

    void* p;
#define SYM(dst, s) cudaGetSymbolAddress(&p, s); float* dst = (float*)p
    SYM(ph,  g_h);  SYM(pq,  g_q);  SYM(pk,  g_k);  SYM(pv,  g_v);
    SYM(ps,  g_s);  SYM(pav, g_av); SYM(px2, g_x2); SYM(ph2, g_h2);
    SYM(pf,  g_f);
    SYM(pwq, g_wq); SYM(pwk, g_wk); SYM(pwv, g_wv); SYM(pwo, g_wo);
    SYM(pw1, g_w1); SYM(pw2, g_w2);
#undef SYM

    // Opt-in to >48KB dynamic smem (idempotent; not a stream op, capture-safe)
    cudaFuncSetAttribute(tf32_gemm<false,false,true>,
        cudaFuncAttributeMaxDynamicSharedMemorySize, SMEM_GEMM);
    cudaFuncSetAttribute(tf32_gemm<true,false,false>,
        cudaFuncAttributeMaxDynamicSharedMemorySize, SMEM_GEMM);
    cudaFuncSetAttribute(tf32_gemm<false,false,false>,
        cudaFuncAttributeMaxDynamicSharedMemorySize, SMEM_GEMM);
    cudaFuncSetAttribute(tf32_gemm<false,true,true>,
        cudaFuncAttributeMaxDynamicSharedMemorySize, SMEM_GEMM);

    // 0. round weights to tf32 (rna)
    round_kernel<<<(DIM*DIM/4 + 255)/256, 256>>>(wq, pwq, DIM*DIM/4);
    round_kernel<<<(DIM*DIM/4 + 255)/256, 256>>>(wk, pwk, DIM*DIM/4);
    round_kernel<<<(DIM*DIM/4 + 255)/256, 256>>>(wv, pwv, DIM*DIM/4);
    round_kernel<<<(DIM*DIM/4 + 255)/256, 256>>>(wo, pwo, DIM*DIM/4);
    round_kernel<<<(DIM*HID/4 + 255)/256, 256>>>(w1, pw1, DIM*HID/4);
    round_kernel<<<(HID*DIM/4 + 255)/256, 256>>>(w2, pw2, HID*DIM/4);

    // 1. h = ln1(x), tf32-rounded
    ln_kernel<<<ROWS, 256>>>(x, ln1_g, ln1_b, ph);

    // 2. q, k, v = h @ {wq, wk, wv}  (rounded outputs)
    {
        dim3 g(DIM/128, ROWS/128, 1);
        tf32_gemm<false,false,true><<<g, 256, SMEM_GEMM>>>(
            ph, pwq, pq, ROWS, DIM, DIM, 0, 0, 0, 1.0f, nullptr, nullptr);
        tf32_gemm<false,false,true><<<g, 256, SMEM_GEMM>>>(
            ph, pwk, pk, ROWS, DIM, DIM, 0, 0, 0, 1.0f, nullptr, nullptr);
        tf32_gemm<false,false,true><<<g, 256, SMEM_GEMM>>>(
            ph, pwv, pv, ROWS, DIM, DIM, 0, 0, 0, 1.0f, nullptr, nullptr);
    }
    // 3. s = (q @ k^T) * 1/32  (fp32 scores)
    tf32_gemm<true,false,false><<<dim3(SEQ/128, SEQ/128, BSZ), 256, SMEM_GEMM>>>(
        pq, pk, ps, SEQ, SEQ, DIM,
        (long long)SEQ*DIM, (long long)SEQ*DIM, (long long)SEQ*SEQ,
        0.03125f, nullptr, nullptr);
    // 4. softmax rows (in place, rounded probs)
    softmax_kernel<<<BSZ*SEQ, 256>>>(ps);
    // 5. av = a @ v  (rounded output)
    tf32_gemm<false,false,true><<<dim3(DIM/128, SEQ/128, BSZ), 256, SMEM_GEMM>>>(
        ps, pv, pav, SEQ, DIM, SEQ,
        (long long)SEQ*SEQ, (long long)SEQ*DIM, (long long)SEQ*DIM,
        1.0f, nullptr, nullptr);
    // 6. x2 = h + av @ wo  (fp32)
    tf32_gemm<false,false,false><<<dim3(DIM/128, ROWS/128, 1), 256, SMEM_GEMM>>>(
        pav, pwo, px2, ROWS, DIM, DIM, 0, 0, 0, 1.0f, nullptr, ph);
    // 7. h2 = ln2(x2), rounded
    ln_kernel<<<ROWS, 256>>>(px2, ln2_g, ln2_b, ph2);
    // 8. f = gelu(h2 @ w1 + b1), rounded
    tf32_gemm<false,true,true><<<dim3(HID/128, ROWS/128, 1), 256, SMEM_GEMM>>>(
        ph2, pw1, pf, ROWS, HID, DIM, 0, 0, 0, 1.0f, b1, nullptr);
    // 9. out = x2 + f @ w2 + b2  (fp32)
    tf32_gemm<false,false,false><<<dim3(DIM/128, ROWS/128, 1), 256, SMEM_GEMM>>>(
        pf, pw2, out, ROWS, DIM, HID, 0, 0, 0, 1.0f, b2, px2);
}

// round 8
// speedup vs baseline: 3.8115x; 1.3244x over previous
#include <cuda_runtime.h>
#include <math.h>
#include <stdint.h>

#define BSZ 8
#define SEQ 2048
#define DIM 1024
#define HID 4096
#define ROWS (BSZ*SEQ)

// ---------------- static device scratch ----------------
static __device__ float g_h [(size_t)ROWS*DIM];
static __device__ float g_q [(size_t)ROWS*DIM];
static __device__ float g_k [(size_t)ROWS*DIM];
static __device__ float g_v [(size_t)ROWS*DIM];
static __device__ float g_s [(size_t)BSZ*SEQ*SEQ];
static __device__ float g_av[(size_t)ROWS*DIM];
static __device__ float g_x2[(size_t)ROWS*DIM];
static __device__ float g_h2[(size_t)ROWS*DIM];
static __device__ float g_f [(size_t)ROWS*HID];
static __device__ float g_wq[(size_t)DIM*DIM];
static __device__ float g_wk[(size_t)DIM*DIM];
static __device__ float g_wv[(size_t)DIM*DIM];
static __device__ float g_wo[(size_t)DIM*DIM];
static __device__ float g_w1[(size_t)DIM*HID];
static __device__ float g_w2[(size_t)HID*DIM];

// ---------------- helpers ----------------
__device__ __forceinline__ uint32_t smem_u32(const void* p) {
    uint32_t a;
    asm("{ .reg .u64 t; cvta.to.shared.u64 t, %1; cvt.u32.u64 %0, t; }" : "=r"(a) : "l"(p));
    return a;
}
__device__ __forceinline__ float rtf32(float v) {
    uint32_t u;
    asm("cvt.rna.tf32.f32 %0, %1;" : "=r"(u) : "f"(v));
    return __uint_as_float(u);
}
__device__ __forceinline__ void cp16(uint32_t dst, const void* src) {
    asm volatile("cp.async.cg.shared.global [%0], [%1], 16;" :: "r"(dst), "l"(src));
}
#define CP_COMMIT() asm volatile("cp.async.commit_group;")
#define CP_WAIT2()  asm volatile("cp.async.wait_group 2;")

#define MMA_TF32(d, a, b) \
    asm volatile("mma.sync.aligned.m16n8k8.row.col.f32.tf32.tf32.f32 " \
        "{%0,%1,%2,%3}, {%4,%5,%6,%7}, {%8,%9}, {%0,%1,%2,%3};" \
        : "+f"((d)[0]), "+f"((d)[1]), "+f"((d)[2]), "+f"((d)[3]) \
        : "r"((a)[0]), "r"((a)[1]), "r"((a)[2]), "r"((a)[3]), \
          "r"((b)[0]), "r"((b)[1]))

// ---------------- tf32 round kernel (weights) ----------------
__global__ __launch_bounds__(256) void round_kernel(
    const float* __restrict__ in, float* __restrict__ out, int n4)
{
    const int idx = blockIdx.x * 256 + threadIdx.x;
    if (idx < n4) {
        float4 v = reinterpret_cast<const float4*>(in)[idx];
        v.x = rtf32(v.x); v.y = rtf32(v.y); v.z = rtf32(v.z); v.w = rtf32(v.w);
        reinterpret_cast<float4*>(out)[idx] = v;
    }
}

// ---------------- LayerNorm (tf32-rounded output) ----------------
__global__ __launch_bounds__(256) void ln_kernel(
    const float* __restrict__ x, const float* __restrict__ g,
    const float* __restrict__ b, float* __restrict__ out)
{
    __shared__ float r0[256], r1[256];
    const int tid = threadIdx.x;
    const size_t row = blockIdx.x;
    const float4 v = reinterpret_cast<const float4*>(x + row * DIM)[tid];
    r0[tid] = v.x + v.y + v.z + v.w;
    r1[tid] = v.x*v.x + v.y*v.y + v.z*v.z + v.w*v.w;
    __syncthreads();
    for (int off = 128; off > 0; off >>= 1) {
        if (tid < off) { r0[tid] += r0[tid+off]; r1[tid] += r1[tid+off]; }
        __syncthreads();
    }
    const float mu  = r0[0] * (1.0f/DIM);
    const float inv = rsqrtf(r1[0] * (1.0f/DIM) - mu*mu + 1e-5f);
    const float4 gg = reinterpret_cast<const float4*>(g)[tid];
    const float4 bb = reinterpret_cast<const float4*>(b)[tid];
    float4 o;
    o.x = rtf32((v.x-mu)*inv*gg.x + bb.x);
    o.y = rtf32((v.y-mu)*inv*gg.y + bb.y);
    o.z = rtf32((v.z-mu)*inv*gg.z + bb.z);
    o.w = rtf32((v.w-mu)*inv*gg.w + bb.w);
    reinterpret_cast<float4*>(out + row * DIM)[tid] = o;
}

// ---------------- softmax (tf32-rounded probs) ----------------
__global__ __launch_bounds__(256) void softmax_kernel(float* __restrict__ sm)
{
    __shared__ float red[256];
    const int tid = threadIdx.x;
    float4* p4 = reinterpret_cast<float4*>(sm + (size_t)blockIdx.x * SEQ);
    float4 v0 = p4[tid], v1 = p4[tid + 256];
    float m = fmaxf(fmaxf(fmaxf(v0.x,v0.y), fmaxf(v0.z,v0.w)),
                    fmaxf(fmaxf(v1.x,v1.y), fmaxf(v1.z,v1.w)));
    red[tid] = m; __syncthreads();
    for (int off = 128; off > 0; off >>= 1) {
        if (tid < off) red[tid] = fmaxf(red[tid], red[tid+off]);
        __syncthreads();
    }
    m = red[0]; __syncthreads();
    v0.x = __expf(v0.x-m); v0.y = __expf(v0.y-m);
    v0.z = __expf(v0.z-m); v0.w = __expf(v0.w-m);
    v1.x = __expf(v1.x-m); v1.y = __expf(v1.y-m);
    v1.z = __expf(v1.z-m); v1.w = __expf(v1.w-m);
    red[tid] = v0.x+v0.y+v0.z+v0.w+v1.x+v1.y+v1.z+v1.w;
    __syncthreads();
    for (int off = 128; off > 0; off >>= 1) {
        if (tid < off) red[tid] += red[tid+off];
        __syncthreads();
    }
    const float inv = 1.0f / red[0];
    v0.x = rtf32(v0.x*inv); v0.y = rtf32(v0.y*inv);
    v0.z = rtf32(v0.z*inv); v0.w = rtf32(v0.w*inv);
    v1.x = rtf32(v1.x*inv); v1.y = rtf32(v1.y*inv);
    v1.z = rtf32(v1.z*inv); v1.w = rtf32(v1.w*inv);
    p4[tid] = v0;
    p4[tid + 256] = v1;
}

// ---------------- TF32 tensor-core GEMM ----------------
// C[M,N] = epi(alpha * A[M,K] @ B) ; B is [K,N] (TRANSB=0) or [N,K] (TRANSB=1).
// Tiles 128x128x16, 8 warps (2x4, warp tile 64x32).
// 4-stage cp.async pipeline, ONE __syncthreads per K-step, 2 CTAs/SM.
#define STAGE_FLOATS 5120               /* 20480 B */
#define NSTAGE 4
#define SMEM_GEMM (NSTAGE * 20480)      /* 81920 B */

template <bool TRANSB>
__device__ __forceinline__ void stage_load(
    uint32_t sbase, int slot, const float* Abase, const float* Bbase,
    int K, int N, int k0, int tid)
{
    const uint32_t sA = sbase + slot * 20480;
    const uint32_t sB = sA + 10240;
#pragma unroll
    for (int h = 0; h < 2; ++h) {
        const int v = tid + h * 256;
        const int row = v >> 2, kv = v & 3;
        cp16(sA + (uint32_t)(row * 80 + kv * 16),
             Abase + (size_t)row * K + k0 + kv * 4);
    }
#pragma unroll
    for (int h = 0; h < 2; ++h) {
        const int v = tid + h * 256;
        if (TRANSB) {
            const int row = v >> 2, kv = v & 3;
            cp16(sB + (uint32_t)(row * 80 + kv * 16),
                 Bbase + (size_t)row * K + k0 + kv * 4);
        } else {
            const int kr = v >> 5, nv = v & 31;
            cp16(sB + (uint32_t)(kr * 544 + nv * 16),
                 Bbase + (size_t)(k0 + kr) * N + nv * 4);
        }
    }
}

template <bool TRANSB, bool GELU, bool ROUND>
__global__ __launch_bounds__(256, 2) void tf32_gemm(
    const float* __restrict__ A, const float* __restrict__ B,
    float* __restrict__ C, int M, int N, int K,
    long long sAa, long long sBb, long long sCc,
    float alpha, const float* __restrict__ bias,
    const float* __restrict__ res)
{
    extern __shared__ float smf[];
    const uint32_t sbase = smem_u32(smf);
    const int tid = threadIdx.x;
    const int lane = tid & 31, wid = tid >> 5;
    const int warpM = wid >> 2, warpN = wid & 3;
    const int lr = lane >> 2, lc = lane & 3;

    const size_t rowBase = (size_t)blockIdx.y * 128;
    const size_t colBase = (size_t)blockIdx.x * 128;
    const float* Abase = A + (size_t)blockIdx.z * sAa + rowBase * K;
    const float* Bbase = TRANSB ? (B + (size_t)blockIdx.z * sBb + colBase * K)
                                : (B + (size_t)blockIdx.z * sBb + colBase);

    float acc[4][4][4];
#pragma unroll
    for (int i = 0; i < 4; ++i)
#pragma unroll
        for (int j = 0; j < 4; ++j)
#pragma unroll
            for (int r = 0; r < 4; ++r) acc[i][j][r] = 0.0f;

    const int KT = K >> 4;
    // prefetch stages 0..NSTAGE-2
    stage_load<TRANSB>(sbase, 0, Abase, Bbase, K, N, 0,  tid); CP_COMMIT();
    stage_load<TRANSB>(sbase, 1, Abase, Bbase, K, N, 16, tid); CP_COMMIT();
    stage_load<TRANSB>(sbase, 2, Abase, Bbase, K, N, 32, tid); CP_COMMIT();

    for (int t = 0; t < KT; ++t) {
        CP_WAIT2();          // stage t data has landed (<=2 younger groups pending)
        __syncthreads();     // stage t visible to all; all warps done reading t-1
        if (t + 3 < KT)      // refill slot (t-1)%4 with stage t+3
            stage_load<TRANSB>(sbase, (t + 3) & 3, Abase, Bbase, K, N, (t + 3) * 16, tid);
        CP_COMMIT();

        const float* As = smf + (size_t)(t & 3) * STAGE_FLOATS;
        const float* Bs = As + 2560;
#pragma unroll
        for (int kk = 0; kk < 2; ++kk) {
            uint32_t af[4][4], bf[4][2];
#pragma unroll
            for (int i = 0; i < 4; ++i) {
                const float* ap = As + (warpM*64 + i*16 + lr) * 20 + kk*8 + lc;
                af[i][0] = __float_as_uint(ap[0]);
                af[i][1] = __float_as_uint(ap[160]);
                af[i][2] = __float_as_uint(ap[4]);
                af[i][3] = __float_as_uint(ap[164]);
            }
#pragma unroll
            for (int j = 0; j < 4; ++j) {
                if (TRANSB) {
                    const float* bp = Bs + (warpN*32 + j*8 + lr) * 20 + kk*8 + lc;
                    bf[j][0] = __float_as_uint(bp[0]);
                    bf[j][1] = __float_as_uint(bp[4]);
                } else {
                    const float* bp = Bs + (kk*8 + lc) * 136 + warpN*32 + j*8 + lr;
                    bf[j][0] = __float_as_uint(bp[0]);
                    bf[j][1] = __float_as_uint(bp[544]);
                }
            }
#pragma unroll
            for (int i = 0; i < 4; ++i)
#pragma unroll
                for (int j = 0; j < 4; ++j)
                    MMA_TF32(acc[i][j], af[i], bf[j]);
        }
    }

    // ---- epilogue ----
    const size_t zC = (size_t)blockIdx.z * sCc;
#pragma unroll
    for (int i = 0; i < 4; ++i) {
        const size_t r0 = rowBase + warpM*64 + i*16 + lr;
#pragma unroll
        for (int half = 0; half < 2; ++half) {
            const size_t r = r0 + half*8;
#pragma unroll
            for (int j = 0; j < 4; ++j) {
                const size_t c = colBase + warpN*32 + j*8 + 2*lc;
                float v0 = acc[i][j][half*2 + 0] * alpha;
                float v1 = acc[i][j][half*2 + 1] * alpha;
                if (bias) { v0 += bias[c]; v1 += bias[c+1]; }
                if (res) {
                    const float2 rv = *reinterpret_cast<const float2*>(res + r*N + c);
                    v0 += rv.x; v1 += rv.y;
                }
                if (GELU) {
                    v0 = 0.5f * v0 * (1.0f + erff(v0 * 0.70710678118654752f));
                    v1 = 0.5f * v1 * (1.0f + erff(v1 * 0.70710678118654752f));
                }
                if (ROUND) { v0 = rtf32(v0); v1 = rtf32(v1); }
                float2 ov = {v0, v1};
                *reinterpret_cast<float2*>(C + zC + r*N + c) = ov;
            }
        }
    }
}

// ---------------- launch ----------------
extern "C" void kernel_launch(void* const* d_in, const int* in_sizes, int n_in,
                              void* d_out, int out_size)
{
    const float* x     = (const float*)d_in[0];
    const float* ln1_g = (const float*)d_in[1];
    const float* ln1_b = (const float*)d_in[2];
    const float* wq    = (const float*)d_in[3];
    const float* wk    = (const float*)d_in[4];
    const float* wv    = (const float*)d_in[5];
    const float* wo    = (const float*)d_in[6];
    const float* ln2_g = (const float*)d_in[7];
    const float* ln2_b = (const float*)d_in[8];
    const float* w1    = (const float*)d_in[9];
    const float* b1    = (const float*)d_in[10];
    const float* w2    = (const float*)d_in[11];
    const float* b2    = (const float*)d_in[12];
    float* out = (float*)d_out;

    void* p;
#define SYM(dst, s) cudaGetSymbolAddress(&p, s); float* dst = (float*)p
    SYM(ph,  g_h);  SYM(pq,  g_q);  SYM(pk,  g_k);  SYM(pv,  g_v);
    SYM(ps,  g_s);  SYM(pav, g_av); SYM(px2, g_x2); SYM(ph2, g_h2);
    SYM(pf,  g_f);
    SYM(pwq, g_wq); SYM(pwk, g_wk); SYM(pwv, g_wv); SYM(pwo, g_wo);
    SYM(pw1, g_w1); SYM(pw2, g_w2);
#undef SYM

    cudaFuncSetAttribute(tf32_gemm<false,false,true>,
        cudaFuncAttributeMaxDynamicSharedMemorySize, SMEM_GEMM);
    cudaFuncSetAttribute(tf32_gemm<true,false,false>,
        cudaFuncAttributeMaxDynamicSharedMemorySize, SMEM_GEMM);
    cudaFuncSetAttribute(tf32_gemm<false,false,false>,
        cudaFuncAttributeMaxDynamicSharedMemorySize, SMEM_GEMM);
    cudaFuncSetAttribute(tf32_gemm<false,true,true>,
        cudaFuncAttributeMaxDynamicSharedMemorySize, SMEM_GEMM);

    // 0. round weights to tf32 (rna)
    round_kernel<<<(DIM*DIM/4 + 255)/256, 256>>>(wq, pwq, DIM*DIM/4);
    round_kernel<<<(DIM*DIM/4 + 255)/256, 256>>>(wk, pwk, DIM*DIM/4);
    round_kernel<<<(DIM*DIM/4 + 255)/256, 256>>>(wv, pwv, DIM*DIM/4);
    round_kernel<<<(DIM*DIM/4 + 255)/256, 256>>>(wo, pwo, DIM*DIM/4);
    round_kernel<<<(DIM*HID/4 + 255)/256, 256>>>(w1, pw1, DIM*HID/4);
    round_kernel<<<(HID*DIM/4 + 255)/256, 256>>>(w2, pw2, HID*DIM/4);

    // 1. h = ln1(x), tf32-rounded
    ln_kernel<<<ROWS, 256>>>(x, ln1_g, ln1_b, ph);

    // 2. q, k, v = h @ {wq, wk, wv}  (rounded outputs)
    {
        dim3 g(DIM/128, ROWS/128, 1);
        tf32_gemm<false,false,true><<<g, 256, SMEM_GEMM>>>(
            ph, pwq, pq, ROWS, DIM, DIM, 0, 0, 0, 1.0f, nullptr, nullptr);
        tf32_gemm<false,false,true><<<g, 256, SMEM_GEMM>>>(
            ph, pwk, pk, ROWS, DIM, DIM, 0, 0, 0, 1.0f, nullptr, nullptr);
        tf32_gemm<false,false,true><<<g, 256, SMEM_GEMM>>>(
            ph, pwv, pv, ROWS, DIM, DIM, 0, 0, 0, 1.0f, nullptr, nullptr);
    }
    // 3. s = (q @ k^T) * 1/32  (fp32 scores)
    tf32_gemm<true,false,false><<<dim3(SEQ/128, SEQ/128, BSZ), 256, SMEM_GEMM>>>(
        pq, pk, ps, SEQ, SEQ, DIM,
        (long long)SEQ*DIM, (long long)SEQ*DIM, (long long)SEQ*SEQ,
        0.03125f, nullptr, nullptr);
    // 4. softmax rows (in place, rounded probs)
    softmax_kernel<<<BSZ*SEQ, 256>>>(ps);
    // 5. av = a @ v  (rounded output)
    tf32_gemm<false,false,true><<<dim3(DIM/128, SEQ/128, BSZ), 256, SMEM_GEMM>>>(
        ps, pv, pav, SEQ, DIM, SEQ,
        (long long)SEQ*SEQ, (long long)SEQ*DIM, (long long)SEQ*DIM,
        1.0f, nullptr, nullptr);
    // 6. x2 = h + av @ wo  (fp32)
    tf32_gemm<false,false,false><<<dim3(DIM/128, ROWS/128, 1), 256, SMEM_GEMM>>>(
        pav, pwo, px2, ROWS, DIM, DIM, 0, 0, 0, 1.0f, nullptr, ph);
    // 7. h2 = ln2(x2), rounded
    ln_kernel<<<ROWS, 256>>>(px2, ln2_g, ln2_b, ph2);
    // 8. f = gelu(h2 @ w1 + b1), rounded
    tf32_gemm<false,true,true><<<dim3(HID/128, ROWS/128, 1), 256, SMEM_GEMM>>>(
        ph2, pw1, pf, ROWS, HID, DIM, 0, 0, 0, 1.0f, b1, nullptr);
    // 9. out = x2 + f @ w2 + b2  (fp32)
    tf32_gemm<false,false,false><<<dim3(DIM/128, ROWS/128, 1), 256, SMEM_GEMM>>>(
        pf, pw2, out, ROWS, DIM, HID, 0, 0, 0, 1.0f, b2, px2);
}